// round 8
// baseline (speedup 1.0000x reference)
#include <cuda_runtime.h>
#include <cstdint>
#include <math.h>

// Shapes (fixed)
#define QL 1024
#define CL 2048
#define BATCH 16
#define DIM 1024

// GEMM tiling
#define BM 128
#define BN 64
#define BK 16
#define SA 20     // A smem row stride (floats): conflict-free fragment LDS
#define SB 20     // B smem row stride (K-contiguous layout only)
#define STAGES 3

// Scratch
__device__ float g_qb [(size_t)BATCH * QL * DIM];              // 64 MB
__device__ float g_ctx[(size_t)BATCH * QL * DIM];              // 64 MB
__device__ float g_ct [(size_t)BATCH * DIM * CL];              // 134 MB: c transposed [b, d, k]

// ---------------------------------------------------------------------------
// helpers
// ---------------------------------------------------------------------------
__device__ __forceinline__ void cp16(uint32_t dst, const float* src) {
    asm volatile("cp.async.cg.shared.global [%0], [%1], 16;" :: "r"(dst), "l"(src));
}
__device__ __forceinline__ void cp_commit() { asm volatile("cp.async.commit_group;" ::: "memory"); }
__device__ __forceinline__ void cp_wait1()  { asm volatile("cp.async.wait_group 1;"  ::: "memory"); }

// 2-way tf32 split: hi = top-10-mantissa truncation, lo = exact residual.
__device__ __forceinline__ void split2(float f, uint32_t& hi, uint32_t& lo) {
    uint32_t u = __float_as_uint(f) & 0xFFFFE000u;
    hi = u;
    lo = __float_as_uint(f - __uint_as_float(u));
}

__device__ __forceinline__ void mma8(float* d, const uint32_t* a, const uint32_t* b) {
    asm volatile(
        "mma.sync.aligned.m16n8k8.row.col.f32.tf32.tf32.f32 "
        "{%0,%1,%2,%3}, {%4,%5,%6,%7}, {%8,%9}, {%0,%1,%2,%3};"
        : "+f"(d[0]), "+f"(d[1]), "+f"(d[2]), "+f"(d[3])
        : "r"(a[0]), "r"(a[1]), "r"(a[2]), "r"(a[3]), "r"(b[0]), "r"(b[1]));
}

// ---------------------------------------------------------------------------
// C[m][n] = sum_k A[m][k] * B[n][k], fp32 in/out, 3xTF32 tensor-core compute.
//   A: row-major, K-contiguous rows, stride lda. CONCAT: [A0|A1] split at Ksplit.
//   B: N rows of K-contiguous data, stride ldb.  (conflict-free LDS pattern)
// Tiles 128x64x16, 256 threads (warps 4m x 2n; warp tile 32x32),
// 3-stage cp.async pipeline.
// ---------------------------------------------------------------------------
template<bool TANH, bool CONCAT>
__global__ __launch_bounds__(256, 2)
void gemm3t_kernel(const float* __restrict__ A0, const float* __restrict__ A1,
                   long lda, long sAb,
                   const float* __restrict__ B, long ldb, long sBb,
                   float* __restrict__ C, long ldc, long sCb,
                   int K, int Ksplit)
{
    __shared__ float As[STAGES][BM * SA];    // 3 x 2560 floats = 30720 B
    __shared__ float Bs[STAGES][BN * SB];    // 3 x 1280 floats = 15360 B

    const int bi = blockIdx.z;
    const float* Ab0 = A0 + (long)bi * sAb;
    const float* Ab1 = CONCAT ? (A1 + (long)bi * sAb) : Ab0;
    const float* Bb  = B + (long)bi * sBb;
    float*       Cb  = C + (long)bi * sCb;

    const int m0 = blockIdx.y * BM;
    const int n0 = blockIdx.x * BN;
    const int tid  = threadIdx.x;
    const int lane = tid & 31;
    const int wid  = tid >> 5;
    const int wm = (wid & 3) * 32;     // warp m offset within block tile
    const int wn = (wid >> 2) * 32;    // warp n offset
    const int g  = lane >> 2;          // groupID (0..7)
    const int t  = lane & 3;           // threadID_in_group (0..3)

    // global->smem load assignments
    const int ar  = tid >> 2;          // 0..63 (rows; A also +64)
    const int akq = (tid & 3) * 4;     // k quad

    const uint32_t sA_base = (uint32_t)__cvta_generic_to_shared(&As[0][0]);
    const uint32_t sB_base = (uint32_t)__cvta_generic_to_shared(&Bs[0][0]);

    float acc[2][4][4];
    #pragma unroll
    for (int i = 0; i < 2; i++)
        #pragma unroll
        for (int j = 0; j < 4; j++)
            #pragma unroll
            for (int r = 0; r < 4; r++) acc[i][j][r] = 0.f;

    const int niter = K / BK;

    auto prefetch = [&](int it, int buf) {
        const int k0 = it * BK;
        const float* Ap; int ka;
        if (CONCAT && k0 >= Ksplit) { Ap = Ab1; ka = k0 - Ksplit; }
        else                        { Ap = Ab0; ka = k0; }
        const uint32_t sa = sA_base + (uint32_t)buf * (BM * SA * 4);
        const float* s0 = Ap + (long)(m0 + ar) * lda + ka + akq;
        cp16(sa + (uint32_t)(ar * SA + akq) * 4, s0);
        cp16(sa + (uint32_t)((ar + 64) * SA + akq) * 4, s0 + 64 * lda);
        const uint32_t sb = sB_base + (uint32_t)buf * (BN * SB * 4);
        cp16(sb + (uint32_t)(ar * SB + akq) * 4,
             Bb + (long)(n0 + ar) * ldb + k0 + akq);
    };

    prefetch(0, 0);
    cp_commit();
    if (niter > 1) prefetch(1, 1);
    cp_commit();

    for (int it = 0; it < niter; it++) {
        const int buf = it % STAGES;
        cp_wait1();
        __syncthreads();
        // prefetch writes buf (it+2)%3 == (it-1)%3, which every warp finished
        // reading before the barrier above.
        if (it + 2 < niter) prefetch(it + 2, (it + 2) % STAGES);
        cp_commit();

        const float* as = &As[buf][0];
        const float* bs = &Bs[buf][0];

        #pragma unroll
        for (int kc = 0; kc < BK; kc += 8) {
            // A fragments (m16n8k8.row layout), split into hi/lo tf32
            uint32_t ah[2][4], al[2][4];
            #pragma unroll
            for (int i = 0; i < 2; i++) {
                const int r0 = wm + i * 16 + g;
                split2(as[r0 * SA + kc + t],           ah[i][0], al[i][0]);
                split2(as[(r0 + 8) * SA + kc + t],     ah[i][1], al[i][1]);
                split2(as[r0 * SA + kc + t + 4],       ah[i][2], al[i][2]);
                split2(as[(r0 + 8) * SA + kc + t + 4], ah[i][3], al[i][3]);
            }
            // B fragments (conflict-free: bank = 20g + t covers all 32 banks)
            uint32_t bh[4][2], bl[4][2];
            #pragma unroll
            for (int j = 0; j < 4; j++) {
                const int n = wn + j * 8 + g;
                split2(bs[n * SB + kc + t],     bh[j][0], bl[j][0]);
                split2(bs[n * SB + kc + t + 4], bh[j][1], bl[j][1]);
            }
            // 3xTF32: D += Ah*Bh + Al*Bh + Ah*Bl
            #pragma unroll
            for (int i = 0; i < 2; i++)
                #pragma unroll
                for (int j = 0; j < 4; j++) {
                    mma8(acc[i][j], ah[i], bh[j]);
                    mma8(acc[i][j], al[i], bh[j]);
                    mma8(acc[i][j], ah[i], bl[j]);
                }
        }
        __syncthreads();
    }

    // epilogue: c0(g,2t) c1(g,2t+1) c2(g+8,2t) c3(g+8,2t+1)
    #pragma unroll
    for (int i = 0; i < 2; i++) {
        const int r0 = m0 + wm + i * 16 + g;
        #pragma unroll
        for (int j = 0; j < 4; j++) {
            const int cc = n0 + wn + j * 8 + t * 2;
            float d0 = acc[i][j][0], d1 = acc[i][j][1];
            float d2 = acc[i][j][2], d3 = acc[i][j][3];
            if (TANH) { d0 = tanhf(d0); d1 = tanhf(d1); d2 = tanhf(d2); d3 = tanhf(d3); }
            *(float2*)&Cb[(long)r0 * ldc + cc]       = make_float2(d0, d1);
            *(float2*)&Cb[(long)(r0 + 8) * ldc + cc] = make_float2(d2, d3);
        }
    }
}

// ---------------------------------------------------------------------------
// Transpose c[CL, B, DIM] -> ct[B, DIM, CL]  (32x32 smem tiles, coalesced both ways)
// ---------------------------------------------------------------------------
__global__ __launch_bounds__(256)
void transpose_c_kernel(const float* __restrict__ c, float* __restrict__ ct)
{
    __shared__ float tile[32][33];
    const int b  = blockIdx.z;
    const int k0 = blockIdx.x * 32;
    const int d0 = blockIdx.y * 32;
    const int tx = threadIdx.x & 31;
    const int ty = threadIdx.x >> 5;   // 0..7

    #pragma unroll
    for (int r = 0; r < 32; r += 8)
        tile[ty + r][tx] = c[(long)(k0 + ty + r) * (BATCH * DIM) + (long)b * DIM + d0 + tx];
    __syncthreads();
    #pragma unroll
    for (int r = 0; r < 32; r += 8)
        ct[((long)b * DIM + d0 + ty + r) * CL + k0 + tx] = tile[tx][ty + r];
}

// ---------------------------------------------------------------------------
// In-place softmax over rows of 2048 (one block per row, 256 threads x 8)
// ---------------------------------------------------------------------------
__global__ __launch_bounds__(256)
void softmax2048_kernel(float* __restrict__ S)
{
    float* row = S + (long)blockIdx.x * 2048;
    const int t = threadIdx.x;
    __shared__ float sred[8];

    float v[8];
    float mx = -3.402823466e38f;
    #pragma unroll
    for (int j = 0; j < 8; j++) {
        v[j] = row[t + j * 256];
        mx = fmaxf(mx, v[j]);
    }
    #pragma unroll
    for (int o = 16; o > 0; o >>= 1)
        mx = fmaxf(mx, __shfl_xor_sync(0xffffffffu, mx, o));
    if ((t & 31) == 0) sred[t >> 5] = mx;
    __syncthreads();
    mx = sred[0];
    #pragma unroll
    for (int w = 1; w < 8; w++) mx = fmaxf(mx, sred[w]);

    float s = 0.f;
    #pragma unroll
    for (int j = 0; j < 8; j++) {
        v[j] = expf(v[j] - mx);
        s += v[j];
    }
    #pragma unroll
    for (int o = 16; o > 0; o >>= 1)
        s += __shfl_xor_sync(0xffffffffu, s, o);
    __syncthreads();
    if ((t & 31) == 0) sred[t >> 5] = s;
    __syncthreads();
    s = 0.f;
    #pragma unroll
    for (int w = 0; w < 8; w++) s += sred[w];

    float inv = 1.f / s;
    #pragma unroll
    for (int j = 0; j < 8; j++)
        row[t + j * 256] = v[j] * inv;
}

// ---------------------------------------------------------------------------
extern "C" void kernel_launch(void* const* d_in, const int* in_sizes, int n_in,
                              void* d_out, int out_size)
{
    (void)in_sizes; (void)n_in; (void)out_size;
    const float* q     = (const float*)d_in[0];   // [QL, B, DIM]
    const float* c     = (const float*)d_in[1];   // [CL, B, DIM]
    const float* W_in  = (const float*)d_in[2];   // [DIM, DIM]
    const float* W_out = (const float*)d_in[3];   // [DIM, 2*DIM]

    float* out   = (float*)d_out;                       // [QL, B, DIM]
    float* score = out + (size_t)QL * BATCH * DIM;      // [B, QL, CL]

    float* qb  = nullptr;
    float* ctx = nullptr;
    float* ct  = nullptr;
    cudaGetSymbolAddress((void**)&qb,  g_qb);
    cudaGetSymbolAddress((void**)&ctx, g_ctx);
    cudaGetSymbolAddress((void**)&ct,  g_ct);

    const long sQB = (long)QL * DIM;
    const long sSC = (long)QL * CL;

    // Stage 0: ct[b,d,k] = c[k,b,d]   (makes stage 4's B K-contiguous)
    {
        dim3 grid(CL / 32, DIM / 32, BATCH);
        transpose_c_kernel<<<grid, 256>>>(c, ct);
    }

    // Stage 1: qb[b,q,e] = sum_d q[q,b,d] * W_in[e,d]
    {
        dim3 grid(DIM / BN, QL / BM, BATCH);
        gemm3t_kernel<false, false><<<grid, 256>>>(
            q, nullptr, (long)BATCH * DIM, DIM,
            W_in, DIM, 0,
            qb, DIM, sQB,
            DIM, 0);
    }

    // Stage 2: raw score[b,q,k] = sum_d qb[b,q,d] * c[k,b,d]
    {
        dim3 grid(CL / BN, QL / BM, BATCH);
        gemm3t_kernel<false, false><<<grid, 256>>>(
            qb, nullptr, DIM, sQB,
            c, (long)BATCH * DIM, DIM,
            score, CL, sSC,
            DIM, 0);
    }

    // Stage 3: softmax in place over last dim (CL=2048)
    softmax2048_kernel<<<BATCH * QL, 256>>>(score);

    // Stage 4: ctx[b,q,d] = sum_k score[b,q,k] * ct[b,d,k]   (now K-contiguous B)
    {
        dim3 grid(DIM / BN, QL / BM, BATCH);
        gemm3t_kernel<false, false><<<grid, 256>>>(
            score, nullptr, CL, sSC,
            ct, CL, (long)DIM * CL,
            ctx, DIM, sQB,
            CL, 0);
    }

    // Stage 5: out[q,b,d] = tanh( sum_f [ctx|qb][b,q,f] * W_out[d,f] )
    {
        dim3 grid(DIM / BN, QL / BM, BATCH);
        gemm3t_kernel<true, true><<<grid, 256>>>(
            ctx, qb, DIM, sQB,
            W_out, 2 * DIM, 0,
            out, (long)BATCH * DIM, DIM,
            2 * DIM, DIM);
    }
}

// round 10
// speedup vs baseline: 1.2464x; 1.2464x over previous
#include <cuda_runtime.h>
#include <cstdint>
#include <math.h>

// Shapes (fixed)
#define QL 1024
#define CL 2048
#define BATCH 16
#define DIM 1024

// GEMM tiling
#define BM 128
#define BN 64
#define BK 16
#define SA 20     // A smem row stride (floats): conflict-free fragment LDS
#define SB 20     // B smem row stride (K-contiguous layout only)
#define STAGES 3

// Scratch
__device__ float g_qb [(size_t)BATCH * QL * DIM];              // 64 MB
__device__ float g_ctx[(size_t)BATCH * QL * DIM];              // 64 MB
__device__ float g_ct [(size_t)BATCH * DIM * CL];              // 134 MB: c transposed [b, d, k]

// ---------------------------------------------------------------------------
// helpers
// ---------------------------------------------------------------------------
__device__ __forceinline__ void cp16(uint32_t dst, const float* src) {
    asm volatile("cp.async.cg.shared.global [%0], [%1], 16;" :: "r"(dst), "l"(src));
}
__device__ __forceinline__ void cp_commit() { asm volatile("cp.async.commit_group;" ::: "memory"); }
__device__ __forceinline__ void cp_wait1()  { asm volatile("cp.async.wait_group 1;"  ::: "memory"); }

// 2-way tf32 split: hi = top-10-mantissa truncation, lo = exact residual.
__device__ __forceinline__ void split2(float f, uint32_t& hi, uint32_t& lo) {
    uint32_t u = __float_as_uint(f) & 0xFFFFE000u;
    hi = u;
    lo = __float_as_uint(f - __uint_as_float(u));
}

__device__ __forceinline__ void mma8(float* d, const uint32_t* a, const uint32_t* b) {
    asm volatile(
        "mma.sync.aligned.m16n8k8.row.col.f32.tf32.tf32.f32 "
        "{%0,%1,%2,%3}, {%4,%5,%6,%7}, {%8,%9}, {%0,%1,%2,%3};"
        : "+f"(d[0]), "+f"(d[1]), "+f"(d[2]), "+f"(d[3])
        : "r"(a[0]), "r"(a[1]), "r"(a[2]), "r"(a[3]), "r"(b[0]), "r"(b[1]));
}

// ---------------------------------------------------------------------------
// C[m][n] = sum_k A[m][k] * B[n][k], fp32 in/out, tensor-core TF32 compute.
//   NSPLIT=3: D += Ah*Bh + Al*Bh + Ah*Bl   (full 3xTF32, rel err ~1e-5 class)
//   NSPLIT=2: D += Ah*B  + Al*B            (A exact, B HW-truncated; ~1.4e-4)
//   A: row-major, K-contiguous rows, stride lda. CONCAT: [A0|A1] split at Ksplit.
//   B: N rows of K-contiguous data, stride ldb.  (conflict-free LDS pattern)
// Tiles 128x64x16, 256 threads (warps 4m x 2n; warp tile 32x32),
// 3-stage cp.async pipeline.
// ---------------------------------------------------------------------------
template<int NSPLIT, bool TANH, bool CONCAT>
__global__ __launch_bounds__(256, 2)
void gemm3t_kernel(const float* __restrict__ A0, const float* __restrict__ A1,
                   long lda, long sAb,
                   const float* __restrict__ B, long ldb, long sBb,
                   float* __restrict__ C, long ldc, long sCb,
                   int K, int Ksplit)
{
    __shared__ float As[STAGES][BM * SA];    // 3 x 2560 floats = 30720 B
    __shared__ float Bs[STAGES][BN * SB];    // 3 x 1280 floats = 15360 B

    const int bi = blockIdx.z;
    const float* Ab0 = A0 + (long)bi * sAb;
    const float* Ab1 = CONCAT ? (A1 + (long)bi * sAb) : Ab0;
    const float* Bb  = B + (long)bi * sBb;
    float*       Cb  = C + (long)bi * sCb;

    const int m0 = blockIdx.y * BM;
    const int n0 = blockIdx.x * BN;
    const int tid  = threadIdx.x;
    const int lane = tid & 31;
    const int wid  = tid >> 5;
    const int wm = (wid & 3) * 32;     // warp m offset within block tile
    const int wn = (wid >> 2) * 32;    // warp n offset
    const int g  = lane >> 2;          // groupID (0..7)
    const int t  = lane & 3;           // threadID_in_group (0..3)

    // global->smem load assignments
    const int ar  = tid >> 2;          // 0..63 (rows; A also +64)
    const int akq = (tid & 3) * 4;     // k quad

    const uint32_t sA_base = (uint32_t)__cvta_generic_to_shared(&As[0][0]);
    const uint32_t sB_base = (uint32_t)__cvta_generic_to_shared(&Bs[0][0]);

    float acc[2][4][4];
    #pragma unroll
    for (int i = 0; i < 2; i++)
        #pragma unroll
        for (int j = 0; j < 4; j++)
            #pragma unroll
            for (int r = 0; r < 4; r++) acc[i][j][r] = 0.f;

    const int niter = K / BK;

    auto prefetch = [&](int it, int buf) {
        const int k0 = it * BK;
        const float* Ap; int ka;
        if (CONCAT && k0 >= Ksplit) { Ap = Ab1; ka = k0 - Ksplit; }
        else                        { Ap = Ab0; ka = k0; }
        const uint32_t sa = sA_base + (uint32_t)buf * (BM * SA * 4);
        const float* s0 = Ap + (long)(m0 + ar) * lda + ka + akq;
        cp16(sa + (uint32_t)(ar * SA + akq) * 4, s0);
        cp16(sa + (uint32_t)((ar + 64) * SA + akq) * 4, s0 + 64 * lda);
        const uint32_t sb = sB_base + (uint32_t)buf * (BN * SB * 4);
        cp16(sb + (uint32_t)(ar * SB + akq) * 4,
             Bb + (long)(n0 + ar) * ldb + k0 + akq);
    };

    prefetch(0, 0);
    cp_commit();
    if (niter > 1) prefetch(1, 1);
    cp_commit();

    for (int it = 0; it < niter; it++) {
        const int buf = it % STAGES;
        cp_wait1();
        __syncthreads();
        // prefetch writes buf (it+2)%3 == (it-1)%3, which every warp finished
        // reading before the barrier above.
        if (it + 2 < niter) prefetch(it + 2, (it + 2) % STAGES);
        cp_commit();

        const float* as = &As[buf][0];
        const float* bs = &Bs[buf][0];

        #pragma unroll
        for (int kc = 0; kc < BK; kc += 8) {
            // A fragments (m16n8k8.row layout), always split hi/lo (exact A)
            uint32_t ah[2][4], al[2][4];
            #pragma unroll
            for (int i = 0; i < 2; i++) {
                const int r0 = wm + i * 16 + g;
                split2(as[r0 * SA + kc + t],           ah[i][0], al[i][0]);
                split2(as[(r0 + 8) * SA + kc + t],     ah[i][1], al[i][1]);
                split2(as[r0 * SA + kc + t + 4],       ah[i][2], al[i][2]);
                split2(as[(r0 + 8) * SA + kc + t + 4], ah[i][3], al[i][3]);
            }
            // B fragments (conflict-free: bank = 20g + t covers all 32 banks)
            uint32_t bh[4][2], bl[4][2];
            #pragma unroll
            for (int j = 0; j < 4; j++) {
                const int n = wn + j * 8 + g;
                const float f0 = bs[n * SB + kc + t];
                const float f1 = bs[n * SB + kc + t + 4];
                if (NSPLIT == 3) {
                    split2(f0, bh[j][0], bl[j][0]);
                    split2(f1, bh[j][1], bl[j][1]);
                } else {
                    bh[j][0] = __float_as_uint(f0);   // HW truncates to tf32
                    bh[j][1] = __float_as_uint(f1);
                }
            }
            #pragma unroll
            for (int i = 0; i < 2; i++)
                #pragma unroll
                for (int j = 0; j < 4; j++) {
                    mma8(acc[i][j], ah[i], bh[j]);
                    mma8(acc[i][j], al[i], bh[j]);
                    if (NSPLIT == 3) mma8(acc[i][j], ah[i], bl[j]);
                }
        }
        __syncthreads();
    }

    // epilogue: c0(g,2t) c1(g,2t+1) c2(g+8,2t) c3(g+8,2t+1)
    #pragma unroll
    for (int i = 0; i < 2; i++) {
        const int r0 = m0 + wm + i * 16 + g;
        #pragma unroll
        for (int j = 0; j < 4; j++) {
            const int cc = n0 + wn + j * 8 + t * 2;
            float d0 = acc[i][j][0], d1 = acc[i][j][1];
            float d2 = acc[i][j][2], d3 = acc[i][j][3];
            if (TANH) { d0 = tanhf(d0); d1 = tanhf(d1); d2 = tanhf(d2); d3 = tanhf(d3); }
            *(float2*)&Cb[(long)r0 * ldc + cc]       = make_float2(d0, d1);
            *(float2*)&Cb[(long)(r0 + 8) * ldc + cc] = make_float2(d2, d3);
        }
    }
}

// ---------------------------------------------------------------------------
// Transpose c[CL, B, DIM] -> ct[B, DIM, CL]  (32x32 smem tiles, coalesced both ways)
// ---------------------------------------------------------------------------
__global__ __launch_bounds__(256)
void transpose_c_kernel(const float* __restrict__ c, float* __restrict__ ct)
{
    __shared__ float tile[32][33];
    const int b  = blockIdx.z;
    const int k0 = blockIdx.x * 32;
    const int d0 = blockIdx.y * 32;
    const int tx = threadIdx.x & 31;
    const int ty = threadIdx.x >> 5;   // 0..7

    #pragma unroll
    for (int r = 0; r < 32; r += 8)
        tile[ty + r][tx] = c[(long)(k0 + ty + r) * (BATCH * DIM) + (long)b * DIM + d0 + tx];
    __syncthreads();
    #pragma unroll
    for (int r = 0; r < 32; r += 8)
        ct[((long)b * DIM + d0 + ty + r) * CL + k0 + tx] = tile[tx][ty + r];
}

// ---------------------------------------------------------------------------
// In-place softmax over rows of 2048 (one block per row, 256 threads x 8)
// ---------------------------------------------------------------------------
__global__ __launch_bounds__(256)
void softmax2048_kernel(float* __restrict__ S)
{
    float* row = S + (long)blockIdx.x * 2048;
    const int t = threadIdx.x;
    __shared__ float sred[8];

    float v[8];
    float mx = -3.402823466e38f;
    #pragma unroll
    for (int j = 0; j < 8; j++) {
        v[j] = row[t + j * 256];
        mx = fmaxf(mx, v[j]);
    }
    #pragma unroll
    for (int o = 16; o > 0; o >>= 1)
        mx = fmaxf(mx, __shfl_xor_sync(0xffffffffu, mx, o));
    if ((t & 31) == 0) sred[t >> 5] = mx;
    __syncthreads();
    mx = sred[0];
    #pragma unroll
    for (int w = 1; w < 8; w++) mx = fmaxf(mx, sred[w]);

    float s = 0.f;
    #pragma unroll
    for (int j = 0; j < 8; j++) {
        v[j] = expf(v[j] - mx);
        s += v[j];
    }
    #pragma unroll
    for (int o = 16; o > 0; o >>= 1)
        s += __shfl_xor_sync(0xffffffffu, s, o);
    __syncthreads();
    if ((t & 31) == 0) sred[t >> 5] = s;
    __syncthreads();
    s = 0.f;
    #pragma unroll
    for (int w = 0; w < 8; w++) s += sred[w];

    float inv = 1.f / s;
    #pragma unroll
    for (int j = 0; j < 8; j++)
        row[t + j * 256] = v[j] * inv;
}

// ---------------------------------------------------------------------------
extern "C" void kernel_launch(void* const* d_in, const int* in_sizes, int n_in,
                              void* d_out, int out_size)
{
    (void)in_sizes; (void)n_in; (void)out_size;
    const float* q     = (const float*)d_in[0];   // [QL, B, DIM]
    const float* c     = (const float*)d_in[1];   // [CL, B, DIM]
    const float* W_in  = (const float*)d_in[2];   // [DIM, DIM]
    const float* W_out = (const float*)d_in[3];   // [DIM, 2*DIM]

    float* out   = (float*)d_out;                       // [QL, B, DIM]
    float* score = out + (size_t)QL * BATCH * DIM;      // [B, QL, CL]

    float* qb  = nullptr;
    float* ctx = nullptr;
    float* ct  = nullptr;
    cudaGetSymbolAddress((void**)&qb,  g_qb);
    cudaGetSymbolAddress((void**)&ctx, g_ctx);
    cudaGetSymbolAddress((void**)&ct,  g_ct);

    const long sQB = (long)QL * DIM;
    const long sSC = (long)QL * CL;

    // Stage 0: ct[b,d,k] = c[k,b,d]   (makes stage 4's B K-contiguous)
    {
        dim3 grid(CL / 32, DIM / 32, BATCH);
        transpose_c_kernel<<<grid, 256>>>(c, ct);
    }

    // Stage 1: qb[b,q,e] = sum_d q[q,b,d] * W_in[e,d]      [3x: feeds logits]
    {
        dim3 grid(DIM / BN, QL / BM, BATCH);
        gemm3t_kernel<3, false, false><<<grid, 256>>>(
            q, nullptr, (long)BATCH * DIM, DIM,
            W_in, DIM, 0,
            qb, DIM, sQB,
            DIM, 0);
    }

    // Stage 2: raw score[b,q,k] = sum_d qb[b,q,d] * c[k,b,d]   [3x: logits]
    {
        dim3 grid(CL / BN, QL / BM, BATCH);
        gemm3t_kernel<3, false, false><<<grid, 256>>>(
            qb, nullptr, DIM, sQB,
            c, (long)BATCH * DIM, DIM,
            score, CL, sSC,
            DIM, 0);
    }

    // Stage 3: softmax in place over last dim (CL=2048)
    softmax2048_kernel<<<BATCH * QL, 256>>>(score);

    // Stage 4: ctx[b,q,d] = sum_k score[b,q,k] * ct[b,d,k]   [2x: post-softmax]
    {
        dim3 grid(DIM / BN, QL / BM, BATCH);
        gemm3t_kernel<2, false, false><<<grid, 256>>>(
            score, nullptr, CL, sSC,
            ct, CL, (long)DIM * CL,
            ctx, DIM, sQB,
            CL, 0);
    }

    // Stage 5: out[q,b,d] = tanh( sum_f [ctx|qb][b,q,f] * W_out[d,f] )  [2x]
    {
        dim3 grid(DIM / BN, QL / BM, BATCH);
        gemm3t_kernel<2, true, true><<<grid, 256>>>(
            ctx, qb, DIM, sQB,
            W_out, 2 * DIM, 0,
            out, (long)BATCH * DIM, DIM,
            2 * DIM, DIM);
    }
}